// round 7
// baseline (speedup 1.0000x reference)
#include <cuda_runtime.h>
#include <cuda_bf16.h>
#include <cuda_fp16.h>
#include <mma.h>
#include <cstdint>

using namespace nvcuda;

// ---------------------------------------------------------------------------
// GraphSAGE 2-layer forward, fully fused per layer:
//   layer kernel = { stage self chunk | gather+mean chunk (from fp16 mirror,
//   computed straight into smem) } -> wmma bf16 split GEMM
//   (Ah@Wh + Al@Wh + Ah@Wl), B fragments loaded directly from global.
// N = 100000, E = 1e6, d_in=64, d_hid=128, d_out=64.
// ---------------------------------------------------------------------------

#define N_NODES 100000
#define E_MAX   1000000
#define D_IN    64
#define D_HID   128
#define D_OUT   64

// Scratch (device globals; no allocation allowed)
__device__ int    g_cnt   [N_NODES];
__device__ int    g_rowptr[N_NODES + 1];
__device__ int    g_cursor[N_NODES];
__device__ int    g_csrsrc[E_MAX];
__device__ __half g_xh    [N_NODES * D_IN];    // fp16 mirror of x
__device__ __half g_h1h   [N_NODES * D_HID];   // fp16 h1 (sole copy)
__device__ __nv_bfloat16 g_B1h[128 * 128];
__device__ __nv_bfloat16 g_B1l[128 * 128];
__device__ __nv_bfloat16 g_B2h[256 * 64];
__device__ __nv_bfloat16 g_B2l[256 * 64];

// bf16 hi/lo packing helpers
__device__ __forceinline__ uint32_t bfu(__nv_bfloat16 h) {
    return (uint32_t)__bfloat16_as_ushort(h);
}
__device__ __forceinline__ uint32_t pack_hi2(float a, float b) {
    return bfu(__float2bfloat16_rn(a)) | (bfu(__float2bfloat16_rn(b)) << 16);
}
__device__ __forceinline__ uint32_t pack_lo2(float a, float b) {
    __nv_bfloat16 ha = __float2bfloat16_rn(a), hb = __float2bfloat16_rn(b);
    float ra = a - __bfloat162float(ha);
    float rb = b - __bfloat162float(hb);
    return bfu(__float2bfloat16_rn(ra)) | (bfu(__float2bfloat16_rn(rb)) << 16);
}

// ===========================================================================
// CSR build
// ===========================================================================
__global__ void zero_int_kernel(int* __restrict__ p, int n) {
    int i = blockIdx.x * blockDim.x + threadIdx.x;
    if (i < n) p[i] = 0;
}

__global__ void count_kernel(const int2* __restrict__ dst2, int* __restrict__ cnt, int E2) {
    int e = blockIdx.x * blockDim.x + threadIdx.x;
    if (e < E2) {
        int2 d = dst2[e];
        atomicAdd(&cnt[d.x], 1);
        atomicAdd(&cnt[d.y], 1);
    }
}

__global__ __launch_bounds__(1024)
void scan_kernel(const int* __restrict__ cnt,
                 int* __restrict__ row_ptr,
                 int* __restrict__ cursor, int n) {
    __shared__ int sums[1024];
    const int tid = threadIdx.x;
    const int chunk = (n + 1023) / 1024;
    const int begin = tid * chunk;
    const int end = min(begin + chunk, n);
    int s = 0;
    for (int i = begin; i < end; i++) s += cnt[i];
    sums[tid] = s;
    __syncthreads();
    for (int off = 1; off < 1024; off <<= 1) {
        int v = 0;
        if (tid >= off) v = sums[tid - off];
        __syncthreads();
        if (tid >= off) sums[tid] += v;
        __syncthreads();
    }
    int prefix = (tid == 0) ? 0 : sums[tid - 1];
    for (int i = begin; i < end; i++) {
        row_ptr[i] = prefix;
        cursor[i] = prefix;
        prefix += cnt[i];
    }
    if (tid == 1023) row_ptr[n] = sums[1023];
}

__global__ void fill_kernel(const int2* __restrict__ src2,
                            const int2* __restrict__ dst2,
                            int* __restrict__ cursor,
                            int* __restrict__ csr, int E2) {
    int e = blockIdx.x * blockDim.x + threadIdx.x;
    if (e < E2) {
        int2 s = src2[e];
        int2 d = dst2[e];
        int p0 = atomicAdd(&cursor[d.x], 1);
        csr[p0] = s.x;
        int p1 = atomicAdd(&cursor[d.y], 1);
        csr[p1] = s.y;
    }
}

// fp32 -> fp16 mirror
__global__ void f2h_kernel(const float4* __restrict__ in,
                           __half2* __restrict__ out, int n4) {
    int i = blockIdx.x * blockDim.x + threadIdx.x;
    if (i >= n4) return;
    float4 v = in[i];
    out[i * 2]     = __floats2half2_rn(v.x, v.y);
    out[i * 2 + 1] = __floats2half2_rn(v.z, v.w);
}

// ===========================================================================
// Weight prep: W = [Ws; Wn] stacked -> hi/lo bf16, row-major [DK2][NOUT]
// ===========================================================================
template <int DK2, int NOUT>
__global__ void wprep_kernel(const float* __restrict__ ws,
                             const float* __restrict__ wn,
                             __nv_bfloat16* __restrict__ Bh,
                             __nv_bfloat16* __restrict__ Bl) {
    int i = blockIdx.x * blockDim.x + threadIdx.x;
    if (i >= DK2 * NOUT) return;
    int k = i / NOUT, n = i % NOUT;
    float w = (k < DK2 / 2) ? ws[k * NOUT + n] : wn[(k - DK2 / 2) * NOUT + n];
    __nv_bfloat16 hi = __float2bfloat16_rn(w);
    Bh[i] = hi;
    Bl[i] = __float2bfloat16_rn(w - __bfloat162float(hi));
}

// ===========================================================================
// Fully fused layer: per K-chunk of 64, stage A into smem as hi/lo bf16:
//   - self chunk: read self features (fp32 x for L1, fp16 h1h for L2)
//   - agg  chunk: GATHER+MEAN computed in registers from fp16 mirror
// then wmma with B fragments straight from global (L1-resident weights).
// CTA = 128 nodes, 8 warps (256 thr). Warp tile (WROWS*16) x (WCOLS*16).
// ===========================================================================
template <int NOUT, int WROWS, int WCOLS, int NCHUNK, int LAYER, bool RELU, bool HALF_OUT>
__global__ __launch_bounds__(256)
void fused_layer_kernel(const float* __restrict__ selff,     // L1: x (fp32)
                        const __half* __restrict__ selfh,    // L2: h1h
                        const uint4* __restrict__ feat,      // gather src (fp16 rows)
                        const int* __restrict__ csr,
                        const int* __restrict__ rowptr,
                        const __nv_bfloat16* __restrict__ Bh,
                        const __nv_bfloat16* __restrict__ Bl,
                        const float* __restrict__ bias,
                        float* __restrict__ out,
                        __half* __restrict__ outh, int nNodes) {
    constexpr int ASTR  = 72;                     // smem A row stride (bf16)
    constexpr int ROWU4 = (LAYER == 1) ? 8 : 16;  // fp16 feature row in uint4
    constexpr int COLG  = NOUT / (WCOLS * 16);    // warp col groups

    extern __shared__ __align__(16) char smem_raw[];
    __nv_bfloat16* sAh = (__nv_bfloat16*)smem_raw;      // 128 x ASTR
    __nv_bfloat16* sAl = sAh + 128 * ASTR;              // 128 x ASTR
    float*         sBias = (float*)(sAl + 128 * ASTR);  // 2048 floats

    const int tid = threadIdx.x;
    const int wid = tid >> 5;
    const int lane = tid & 31;
    const int rowg = wid / COLG;
    const int colg = wid % COLG;
    const int base = blockIdx.x * 128;

    for (int i = tid; i < 16 * NOUT; i += 256) sBias[i] = bias[i % NOUT];
    __syncthreads();

    wmma::fragment<wmma::accumulator, 16, 16, 16, float> acc[WROWS][WCOLS];
#pragma unroll
    for (int r = 0; r < WROWS; r++)
#pragma unroll
        for (int c = 0; c < WCOLS; c++)
            wmma::load_matrix_sync(acc[r][c],
                sBias + (colg * WCOLS + c) * 16, NOUT, wmma::mem_row_major);

    for (int kc = 0; kc < NCHUNK; kc++) {
        __syncthreads();   // frag loads of previous chunk done before overwrite

        const bool is_agg = (LAYER == 1) ? (kc == 1) : (kc >= 2);
        if (is_agg) {
            // ---- gather + mean straight into smem staging ----
            const int qoff = (LAYER == 1) ? 0 : (kc - 2) * 8;  // uint4 col offset
            const int c = tid & 7;                             // 8 threads/node
#pragma unroll
            for (int pass = 0; pass < 4; pass++) {
                int slot = pass * 32 + (tid >> 3);
                int node = base + slot;
                float a0 = 0.f, a1 = 0.f, a2 = 0.f, a3 = 0.f;
                float a4 = 0.f, a5 = 0.f, a6 = 0.f, a7 = 0.f;
                if (node < nNodes) {
                    const int b = rowptr[node];
                    const int e = rowptr[node + 1];
#pragma unroll 4
                    for (int i = b; i < e; i++) {
                        int s = __ldg(&csr[i]);
                        uint4 r = __ldg(&feat[(size_t)s * ROWU4 + qoff + c]);
                        const __half2* ph = reinterpret_cast<const __half2*>(&r);
                        float2 f0 = __half22float2(ph[0]);
                        float2 f1 = __half22float2(ph[1]);
                        float2 f2 = __half22float2(ph[2]);
                        float2 f3 = __half22float2(ph[3]);
                        a0 += f0.x; a1 += f0.y; a2 += f1.x; a3 += f1.y;
                        a4 += f2.x; a5 += f2.y; a6 += f3.x; a7 += f3.y;
                    }
                    int d = e - b;
                    float inv = 1.0f / (float)(d > 1 ? d : 1);
                    a0 *= inv; a1 *= inv; a2 *= inv; a3 *= inv;
                    a4 *= inv; a5 *= inv; a6 *= inv; a7 *= inv;
                }
                uint4 hp = make_uint4(pack_hi2(a0, a1), pack_hi2(a2, a3),
                                      pack_hi2(a4, a5), pack_hi2(a6, a7));
                uint4 lp = make_uint4(pack_lo2(a0, a1), pack_lo2(a2, a3),
                                      pack_lo2(a4, a5), pack_lo2(a6, a7));
                *reinterpret_cast<uint4*>(&sAh[slot * ASTR + c * 8]) = hp;
                *reinterpret_cast<uint4*>(&sAl[slot * ASTR + c * 8]) = lp;
            }
        } else if (LAYER == 2) {
            // ---- self chunk from fp16 h1h ----
#pragma unroll
            for (int jj = tid; jj < 1024; jj += 256) {
                int m = jj >> 3, c8 = jj & 7;
                int node = base + m;
                uint4 raw = make_uint4(0, 0, 0, 0);
                if (node < nNodes)
                    raw = *reinterpret_cast<const uint4*>(
                        selfh + (size_t)node * 128 + kc * 64 + c8 * 8);
                const __half2* ph = reinterpret_cast<const __half2*>(&raw);
                float f[8];
#pragma unroll
                for (int q = 0; q < 4; q++) {
                    float2 v = __half22float2(ph[q]);
                    f[2 * q] = v.x; f[2 * q + 1] = v.y;
                }
                uint4 hp = make_uint4(pack_hi2(f[0], f[1]), pack_hi2(f[2], f[3]),
                                      pack_hi2(f[4], f[5]), pack_hi2(f[6], f[7]));
                uint4 lp = make_uint4(pack_lo2(f[0], f[1]), pack_lo2(f[2], f[3]),
                                      pack_lo2(f[4], f[5]), pack_lo2(f[6], f[7]));
                *reinterpret_cast<uint4*>(&sAh[m * ASTR + c8 * 8]) = hp;
                *reinterpret_cast<uint4*>(&sAl[m * ASTR + c8 * 8]) = lp;
            }
        } else {
            // ---- self chunk from fp32 x ----
#pragma unroll
            for (int jj = tid; jj < 2048; jj += 256) {
                int m = jj >> 4, c4 = jj & 15;
                int node = base + m;
                float4 v = make_float4(0.f, 0.f, 0.f, 0.f);
                if (node < nNodes)
                    v = *reinterpret_cast<const float4*>(
                            selff + (size_t)node * 64 + c4 * 4);
                uint2 hp = make_uint2(pack_hi2(v.x, v.y), pack_hi2(v.z, v.w));
                uint2 lp = make_uint2(pack_lo2(v.x, v.y), pack_lo2(v.z, v.w));
                *reinterpret_cast<uint2*>(&sAh[m * ASTR + c4 * 4]) = hp;
                *reinterpret_cast<uint2*>(&sAl[m * ASTR + c4 * 4]) = lp;
            }
        }
        __syncthreads();

        // ---- MMA over 4 k-steps of 16; B fragments from global ----
#pragma unroll
        for (int kk = 0; kk < 4; kk++) {
            wmma::fragment<wmma::matrix_a, 16, 16, 16, __nv_bfloat16, wmma::row_major> ah[WROWS], al[WROWS];
#pragma unroll
            for (int r = 0; r < WROWS; r++) {
                int rr = (rowg * WROWS + r) * 16;
                wmma::load_matrix_sync(ah[r], sAh + rr * ASTR + kk * 16, ASTR);
                wmma::load_matrix_sync(al[r], sAl + rr * ASTR + kk * 16, ASTR);
            }
#pragma unroll
            for (int c = 0; c < WCOLS; c++) {
                wmma::fragment<wmma::matrix_b, 16, 16, 16, __nv_bfloat16, wmma::row_major> bh, bl;
                int cc = (colg * WCOLS + c) * 16;
                size_t boff = (size_t)(kc * 64 + kk * 16) * NOUT + cc;
                wmma::load_matrix_sync(bh, Bh + boff, NOUT);
                wmma::load_matrix_sync(bl, Bl + boff, NOUT);
#pragma unroll
                for (int r = 0; r < WROWS; r++) {
                    wmma::mma_sync(acc[r][c], ah[r], bh, acc[r][c]);
                    wmma::mma_sync(acc[r][c], al[r], bh, acc[r][c]);
                    wmma::mma_sync(acc[r][c], ah[r], bl, acc[r][c]);
                }
            }
        }
    }

    // ---- epilogue ----
    float* scratch = sBias + wid * 256;   // per-warp 16x16 fp32 tile
#pragma unroll
    for (int r = 0; r < WROWS; r++) {
        int rbase = base + (rowg * WROWS + r) * 16;
        if (rbase < nNodes) {
#pragma unroll
            for (int c = 0; c < WCOLS; c++) {
                if (RELU) {
#pragma unroll
                    for (int i = 0; i < acc[r][c].num_elements; i++)
                        acc[r][c].x[i] = fmaxf(acc[r][c].x[i], 0.f);
                }
                int cc = (colg * WCOLS + c) * 16;
                if (HALF_OUT) {
                    __syncwarp();
                    wmma::store_matrix_sync(scratch, acc[r][c], 16,
                                            wmma::mem_row_major);
                    __syncwarp();
                    int lr = lane >> 1, lc = (lane & 1) * 8;
                    float4 va = *reinterpret_cast<float4*>(&scratch[lr * 16 + lc]);
                    float4 vb = *reinterpret_cast<float4*>(&scratch[lr * 16 + lc + 4]);
                    __half2 h0 = __floats2half2_rn(va.x, va.y);
                    __half2 h1 = __floats2half2_rn(va.z, va.w);
                    __half2 h2 = __floats2half2_rn(vb.x, vb.y);
                    __half2 h3 = __floats2half2_rn(vb.z, vb.w);
                    uint4 packed = make_uint4(
                        *(uint32_t*)&h0, *(uint32_t*)&h1,
                        *(uint32_t*)&h2, *(uint32_t*)&h3);
                    *reinterpret_cast<uint4*>(
                        &outh[(size_t)(rbase + lr) * NOUT + cc + lc]) = packed;
                } else {
                    wmma::store_matrix_sync(
                        out + (size_t)rbase * NOUT + cc,
                        acc[r][c], NOUT, wmma::mem_row_major);
                }
            }
        }
    }
}

// ===========================================================================
extern "C" void kernel_launch(void* const* d_in, const int* in_sizes, int n_in,
                              void* d_out, int out_size) {
    const float* x        = (const float*)d_in[0];
    const int*   src      = (const int*)d_in[1];
    const int*   dst      = (const int*)d_in[2];
    const float* w_self1  = (const float*)d_in[3];
    const float* w_neigh1 = (const float*)d_in[4];
    const float* b1       = (const float*)d_in[5];
    const float* w_self2  = (const float*)d_in[6];
    const float* w_neigh2 = (const float*)d_in[7];
    const float* b2       = (const float*)d_in[8];
    float* out = (float*)d_out;

    const int E = in_sizes[1];

    int *cnt, *rowptr, *cursor, *csrsrc;
    __half *xh, *h1h;
    __nv_bfloat16 *B1h, *B1l, *B2h, *B2l;
    cudaGetSymbolAddress((void**)&cnt,    g_cnt);
    cudaGetSymbolAddress((void**)&rowptr, g_rowptr);
    cudaGetSymbolAddress((void**)&cursor, g_cursor);
    cudaGetSymbolAddress((void**)&csrsrc, g_csrsrc);
    cudaGetSymbolAddress((void**)&xh,     g_xh);
    cudaGetSymbolAddress((void**)&h1h,    g_h1h);
    cudaGetSymbolAddress((void**)&B1h,    g_B1h);
    cudaGetSymbolAddress((void**)&B1l,    g_B1l);
    cudaGetSymbolAddress((void**)&B2h,    g_B2h);
    cudaGetSymbolAddress((void**)&B2l,    g_B2l);

    // smem: A hi/lo (2 x 128 x 72 bf16) + 2048-float bias/scratch region
    constexpr int SMEM_FUSED = 2 * 128 * 72 * 2 + 2048 * 4;   // 45056
    cudaFuncSetAttribute(
        (const void*)fused_layer_kernel<D_HID, 2, 4, 2, 1, true, true>,
        cudaFuncAttributeMaxDynamicSharedMemorySize, SMEM_FUSED);
    cudaFuncSetAttribute(
        (const void*)fused_layer_kernel<D_OUT, 1, 4, 4, 2, false, false>,
        cudaFuncAttributeMaxDynamicSharedMemorySize, SMEM_FUSED);

    const int nTiles = (N_NODES + 127) / 128;
    const int E2 = E / 2;   // E is even (1e6)

    // --- CSR build ---
    zero_int_kernel<<<(N_NODES + 255) / 256, 256>>>(cnt, N_NODES);
    count_kernel<<<(E2 + 255) / 256, 256>>>((const int2*)dst, cnt, E2);
    scan_kernel<<<1, 1024>>>(cnt, rowptr, cursor, N_NODES);
    fill_kernel<<<(E2 + 255) / 256, 256>>>(
        (const int2*)src, (const int2*)dst, cursor, csrsrc, E2);

    // --- weight prep + x fp16 mirror (tiny) ---
    wprep_kernel<128, 128><<<(128 * 128 + 255) / 256, 256>>>(w_self1, w_neigh1, B1h, B1l);
    wprep_kernel<256, 64><<<(256 * 64 + 255) / 256, 256>>>(w_self2, w_neigh2, B2h, B2l);
    f2h_kernel<<<(N_NODES * D_IN / 4 + 255) / 256, 256>>>(
        (const float4*)x, (__half2*)xh, N_NODES * D_IN / 4);

    // --- Layer 1 (fused gather + GEMM), fp16 output only ---
    fused_layer_kernel<D_HID, 2, 4, 2, 1, true, true><<<nTiles, 256, SMEM_FUSED>>>(
        x, nullptr, (const uint4*)xh, csrsrc, rowptr,
        B1h, B1l, b1, nullptr, h1h, N_NODES);

    // --- Layer 2 (fused gather + GEMM), fp32 output ---
    fused_layer_kernel<D_OUT, 1, 4, 4, 2, false, false><<<nTiles, 256, SMEM_FUSED>>>(
        nullptr, h1h, (const uint4*)h1h, csrsrc, rowptr,
        B2h, B2l, b2, out, nullptr, N_NODES);
}

// round 8
// speedup vs baseline: 1.2911x; 1.2911x over previous
#include <cuda_runtime.h>
#include <cuda_bf16.h>
#include <cuda_fp16.h>
#include <mma.h>
#include <cstdint>

using namespace nvcuda;

// ---------------------------------------------------------------------------
// GraphSAGE 2-layer forward.
//   CSR-gather aggregation over fp16 feature mirrors, with shuffle-broadcast
//   of edge indices (1 coalesced csr load per TPN edges instead of TPN
//   redundant loads). wmma bf16 split GEMM (Ah@Wh + Al@Wh + Ah@Wl).
//   h1 kept ONLY in fp16 (exact under bf16 hi/lo split for the GEMM).
// N = 100000, E = 1e6, d_in=64, d_hid=128, d_out=64.
// ---------------------------------------------------------------------------

#define N_NODES 100000
#define E_MAX   1000000
#define D_IN    64
#define D_HID   128
#define D_OUT   64

// Scratch (device globals; no allocation allowed)
__device__ int    g_cnt   [N_NODES];
__device__ int    g_rowptr[N_NODES + 1];
__device__ int    g_cursor[N_NODES];
__device__ int    g_csrsrc[E_MAX];
__device__ float  g_agg1  [N_NODES * D_IN];
__device__ float  g_agg2  [N_NODES * D_HID];
__device__ __half g_xh    [N_NODES * D_IN];    // fp16 mirror of x
__device__ __half g_h1h   [N_NODES * D_HID];   // fp16 h1 (sole copy)
__device__ __nv_bfloat16 g_B1h[128 * 128];
__device__ __nv_bfloat16 g_B1l[128 * 128];
__device__ __nv_bfloat16 g_B2h[256 * 64];
__device__ __nv_bfloat16 g_B2l[256 * 64];

// bf16 hi/lo packing helpers
__device__ __forceinline__ uint32_t bfu(__nv_bfloat16 h) {
    return (uint32_t)__bfloat16_as_ushort(h);
}
__device__ __forceinline__ uint32_t pack_hi2(float a, float b) {
    return bfu(__float2bfloat16_rn(a)) | (bfu(__float2bfloat16_rn(b)) << 16);
}
__device__ __forceinline__ uint32_t pack_lo2(float a, float b) {
    __nv_bfloat16 ha = __float2bfloat16_rn(a), hb = __float2bfloat16_rn(b);
    float ra = a - __bfloat162float(ha);
    float rb = b - __bfloat162float(hb);
    return bfu(__float2bfloat16_rn(ra)) | (bfu(__float2bfloat16_rn(rb)) << 16);
}

// ===========================================================================
// CSR build
// ===========================================================================
__global__ void zero_int_kernel(int* __restrict__ p, int n) {
    int i = blockIdx.x * blockDim.x + threadIdx.x;
    if (i < n) p[i] = 0;
}

__global__ void count_kernel(const int2* __restrict__ dst2, int* __restrict__ cnt, int E2) {
    int e = blockIdx.x * blockDim.x + threadIdx.x;
    if (e < E2) {
        int2 d = dst2[e];
        atomicAdd(&cnt[d.x], 1);
        atomicAdd(&cnt[d.y], 1);
    }
}

__global__ __launch_bounds__(1024)
void scan_kernel(const int* __restrict__ cnt,
                 int* __restrict__ row_ptr,
                 int* __restrict__ cursor, int n) {
    __shared__ int sums[1024];
    const int tid = threadIdx.x;
    const int chunk = (n + 1023) / 1024;
    const int begin = tid * chunk;
    const int end = min(begin + chunk, n);
    int s = 0;
    for (int i = begin; i < end; i++) s += cnt[i];
    sums[tid] = s;
    __syncthreads();
    for (int off = 1; off < 1024; off <<= 1) {
        int v = 0;
        if (tid >= off) v = sums[tid - off];
        __syncthreads();
        if (tid >= off) sums[tid] += v;
        __syncthreads();
    }
    int prefix = (tid == 0) ? 0 : sums[tid - 1];
    for (int i = begin; i < end; i++) {
        row_ptr[i] = prefix;
        cursor[i] = prefix;
        prefix += cnt[i];
    }
    if (tid == 1023) row_ptr[n] = sums[1023];
}

__global__ void fill_kernel(const int2* __restrict__ src2,
                            const int2* __restrict__ dst2,
                            int* __restrict__ cursor,
                            int* __restrict__ csr, int E2) {
    int e = blockIdx.x * blockDim.x + threadIdx.x;
    if (e < E2) {
        int2 s = src2[e];
        int2 d = dst2[e];
        int p0 = atomicAdd(&cursor[d.x], 1);
        csr[p0] = s.x;
        int p1 = atomicAdd(&cursor[d.y], 1);
        csr[p1] = s.y;
    }
}

// fp32 -> fp16 mirror
__global__ void f2h_kernel(const float4* __restrict__ in,
                           __half2* __restrict__ out, int n4) {
    int i = blockIdx.x * blockDim.x + threadIdx.x;
    if (i >= n4) return;
    float4 v = in[i];
    out[i * 2]     = __floats2half2_rn(v.x, v.y);
    out[i * 2 + 1] = __floats2half2_rn(v.z, v.w);
}

// ===========================================================================
// Gather + mean over fp16 features, shuffle-broadcast edge indices.
// TPN lanes per node (TPN uint4 per feature row). Per batch of up to TPN
// edges: one coalesced csr load, then TPN shfl-broadcasts; each lane does
// exactly one LDG.128 per edge. fp32 accumulation.
// ===========================================================================
template <int TPN>
__global__ __launch_bounds__(256)
void gather_h_kernel(const uint4* __restrict__ feat,
                     const int* __restrict__ csr,
                     const int* __restrict__ row_ptr,
                     float* __restrict__ aggmean, int n) {
    const int tid = threadIdx.x;
    const int lane = tid & 31;
    const int group = lane / TPN;          // node group within warp
    const int c = lane % TPN;              // uint4 column within row
    const int node = blockIdx.x * (256 / TPN) + (tid >> 5) * (32 / TPN) + group;
    if (node >= n) return;
    const unsigned mask =
        (TPN == 32) ? 0xFFFFFFFFu : (((1u << TPN) - 1u) << (group * TPN));

    const int b = row_ptr[node];
    const int e = row_ptr[node + 1];
    float acc[8];
#pragma unroll
    for (int q = 0; q < 8; q++) acc[q] = 0.f;

    for (int batch = b; batch < e; batch += TPN) {
        int m = batch + c;
        int idx = (m < e) ? __ldg(&csr[m]) : 0;
        int cnt = min(TPN, e - batch);
        for (int j = 0; j < cnt; j++) {
            int s = __shfl_sync(mask, idx, group * TPN + j);
            uint4 r = __ldg(&feat[(size_t)s * TPN + c]);
            const __half2* ph = reinterpret_cast<const __half2*>(&r);
#pragma unroll
            for (int q = 0; q < 4; q++) {
                float2 f = __half22float2(ph[q]);
                acc[2 * q]     += f.x;
                acc[2 * q + 1] += f.y;
            }
        }
    }
    int d = e - b;
    float inv = 1.0f / (float)(d > 1 ? d : 1);
    float* dst = aggmean + (size_t)node * (TPN * 8) + c * 8;
    *reinterpret_cast<float4*>(dst) =
        make_float4(acc[0] * inv, acc[1] * inv, acc[2] * inv, acc[3] * inv);
    *reinterpret_cast<float4*>(dst + 4) =
        make_float4(acc[4] * inv, acc[5] * inv, acc[6] * inv, acc[7] * inv);
}

// ===========================================================================
// Weight prep: W = [Ws; Wn] stacked -> hi/lo bf16, row-major [DK2][NOUT]
// ===========================================================================
template <int DK2, int NOUT>
__global__ void wprep_kernel(const float* __restrict__ ws,
                             const float* __restrict__ wn,
                             __nv_bfloat16* __restrict__ Bh,
                             __nv_bfloat16* __restrict__ Bl) {
    int i = blockIdx.x * blockDim.x + threadIdx.x;
    if (i >= DK2 * NOUT) return;
    int k = i / NOUT, n = i % NOUT;
    float w = (k < DK2 / 2) ? ws[k * NOUT + n] : wn[(k - DK2 / 2) * NOUT + n];
    __nv_bfloat16 hi = __float2bfloat16_rn(w);
    Bh[i] = hi;
    Bl[i] = __float2bfloat16_rn(w - __bfloat162float(hi));
}

// ===========================================================================
// Fused layer via wmma bf16 split GEMM (Round-6 structure).
// CTA = 128 nodes x NOUT, 8 warps. Warp tile (WROWS*16) x (WCOLS*16).
// LAYER==1: self = fp32 x,   agg = fp32 agg1.  Output: fp16 h1h only.
// LAYER==2: self = fp16 h1h, agg = fp32 agg2.  Output: fp32 d_out.
// ===========================================================================
template <int NOUT, int WROWS, int WCOLS, int NCHUNK, int LAYER, bool RELU, bool HALF_OUT>
__global__ __launch_bounds__(256)
void wmma_layer_kernel(const float* __restrict__ self,
                       const __half* __restrict__ selfh,
                       const float* __restrict__ agg,
                       const __nv_bfloat16* __restrict__ Bh,
                       const __nv_bfloat16* __restrict__ Bl,
                       const float* __restrict__ bias,
                       float* __restrict__ out,
                       __half* __restrict__ outh, int nNodes) {
    constexpr int LD    = (LAYER == 1) ? 64 : 128;   // fp32 source row stride
    constexpr int ASTR  = 72;                        // smem A row stride (bf16)
    constexpr int BSTR  = NOUT + 8;                  // smem B row stride (bf16)
    constexpr int COLG  = NOUT / (WCOLS * 16);       // warp col groups

    extern __shared__ __align__(16) char smem_raw[];
    __nv_bfloat16* sAh = (__nv_bfloat16*)smem_raw;          // 128 x ASTR
    __nv_bfloat16* sAl = sAh + 128 * ASTR;                  // 128 x ASTR
    __nv_bfloat16* sBh = sAl + 128 * ASTR;                  // 64 x BSTR
    __nv_bfloat16* sBl = sBh + 64 * BSTR;                   // 64 x BSTR
    float*         sBias = (float*)(sBl + 64 * BSTR);       // 16 x NOUT (>= 8*256 floats)

    const int tid = threadIdx.x;
    const int wid = tid >> 5;
    const int lane = tid & 31;
    const int rowg = wid / COLG;
    const int colg = wid % COLG;
    const int base = blockIdx.x * 128;

    for (int i = tid; i < 16 * NOUT; i += 256) sBias[i] = bias[i % NOUT];
    __syncthreads();

    wmma::fragment<wmma::accumulator, 16, 16, 16, float> acc[WROWS][WCOLS];
#pragma unroll
    for (int r = 0; r < WROWS; r++)
#pragma unroll
        for (int c = 0; c < WCOLS; c++)
            wmma::load_matrix_sync(acc[r][c],
                sBias + (colg * WCOLS + c) * 16, NOUT, wmma::mem_row_major);

    for (int kc = 0; kc < NCHUNK; kc++) {
        __syncthreads();

        // ---- stage A: 128 x 64 -> hi/lo bf16 ----
        bool half_src = (LAYER == 2) && (kc < 2);
        if (half_src) {
#pragma unroll
            for (int jj = tid; jj < 1024; jj += 256) {
                int m = jj >> 3, c8 = jj & 7;
                int node = base + m;
                uint4 raw = make_uint4(0, 0, 0, 0);
                if (node < nNodes)
                    raw = *reinterpret_cast<const uint4*>(
                        selfh + (size_t)node * 128 + kc * 64 + c8 * 8);
                const __half2* ph = reinterpret_cast<const __half2*>(&raw);
                float f[8];
#pragma unroll
                for (int q = 0; q < 4; q++) {
                    float2 v = __half22float2(ph[q]);
                    f[2 * q] = v.x; f[2 * q + 1] = v.y;
                }
                uint4 hp = make_uint4(pack_hi2(f[0], f[1]), pack_hi2(f[2], f[3]),
                                      pack_hi2(f[4], f[5]), pack_hi2(f[6], f[7]));
                uint4 lp = make_uint4(pack_lo2(f[0], f[1]), pack_lo2(f[2], f[3]),
                                      pack_lo2(f[4], f[5]), pack_lo2(f[6], f[7]));
                *reinterpret_cast<uint4*>(&sAh[m * ASTR + c8 * 8]) = hp;
                *reinterpret_cast<uint4*>(&sAl[m * ASTR + c8 * 8]) = lp;
            }
        } else {
            const float* srcp;
            int coloff;
            if (LAYER == 1) { srcp = kc ? agg : self; coloff = 0; }
            else            { srcp = agg; coloff = (kc - 2) * 64; }
#pragma unroll
            for (int jj = tid; jj < 2048; jj += 256) {
                int m = jj >> 4, c4 = jj & 15;
                int node = base + m;
                float4 v = make_float4(0.f, 0.f, 0.f, 0.f);
                if (node < nNodes)
                    v = *reinterpret_cast<const float4*>(
                            srcp + (size_t)node * LD + coloff + c4 * 4);
                uint2 hp = make_uint2(pack_hi2(v.x, v.y), pack_hi2(v.z, v.w));
                uint2 lp = make_uint2(pack_lo2(v.x, v.y), pack_lo2(v.z, v.w));
                *reinterpret_cast<uint2*>(&sAh[m * ASTR + c4 * 4]) = hp;
                *reinterpret_cast<uint2*>(&sAl[m * ASTR + c4 * 4]) = lp;
            }
        }
        // ---- stage B: 64 x NOUT hi/lo bf16 ----
#pragma unroll
        for (int jj = tid; jj < 64 * NOUT / 4; jj += 256) {
            int r = jj / (NOUT / 4), c4 = jj % (NOUT / 4);
            size_t g = (size_t)(kc * 64 + r) * NOUT + c4 * 4;
            *reinterpret_cast<uint2*>(&sBh[r * BSTR + c4 * 4]) =
                *reinterpret_cast<const uint2*>(&Bh[g]);
            *reinterpret_cast<uint2*>(&sBl[r * BSTR + c4 * 4]) =
                *reinterpret_cast<const uint2*>(&Bl[g]);
        }
        __syncthreads();

#pragma unroll
        for (int kk = 0; kk < 4; kk++) {
            wmma::fragment<wmma::matrix_a, 16, 16, 16, __nv_bfloat16, wmma::row_major> ah[WROWS], al[WROWS];
#pragma unroll
            for (int r = 0; r < WROWS; r++) {
                int rr = (rowg * WROWS + r) * 16;
                wmma::load_matrix_sync(ah[r], sAh + rr * ASTR + kk * 16, ASTR);
                wmma::load_matrix_sync(al[r], sAl + rr * ASTR + kk * 16, ASTR);
            }
#pragma unroll
            for (int c = 0; c < WCOLS; c++) {
                wmma::fragment<wmma::matrix_b, 16, 16, 16, __nv_bfloat16, wmma::row_major> bh, bl;
                int cc = (colg * WCOLS + c) * 16;
                wmma::load_matrix_sync(bh, sBh + kk * 16 * BSTR + cc, BSTR);
                wmma::load_matrix_sync(bl, sBl + kk * 16 * BSTR + cc, BSTR);
#pragma unroll
                for (int r = 0; r < WROWS; r++) {
                    wmma::mma_sync(acc[r][c], ah[r], bh, acc[r][c]);
                    wmma::mma_sync(acc[r][c], al[r], bh, acc[r][c]);
                    wmma::mma_sync(acc[r][c], ah[r], bl, acc[r][c]);
                }
            }
        }
    }

    // ---- epilogue ----
    float* scratch = sBias + wid * 256;   // per-warp 16x16 fp32 tile
#pragma unroll
    for (int r = 0; r < WROWS; r++) {
        int rbase = base + (rowg * WROWS + r) * 16;
        if (rbase < nNodes) {
#pragma unroll
            for (int c = 0; c < WCOLS; c++) {
                if (RELU) {
#pragma unroll
                    for (int i = 0; i < acc[r][c].num_elements; i++)
                        acc[r][c].x[i] = fmaxf(acc[r][c].x[i], 0.f);
                }
                int cc = (colg * WCOLS + c) * 16;
                if (HALF_OUT) {
                    __syncwarp();
                    wmma::store_matrix_sync(scratch, acc[r][c], 16,
                                            wmma::mem_row_major);
                    __syncwarp();
                    int lr = lane >> 1, lc = (lane & 1) * 8;
                    float4 va = *reinterpret_cast<float4*>(&scratch[lr * 16 + lc]);
                    float4 vb = *reinterpret_cast<float4*>(&scratch[lr * 16 + lc + 4]);
                    __half2 h0 = __floats2half2_rn(va.x, va.y);
                    __half2 h1 = __floats2half2_rn(va.z, va.w);
                    __half2 h2 = __floats2half2_rn(vb.x, vb.y);
                    __half2 h3 = __floats2half2_rn(vb.z, vb.w);
                    uint4 packed = make_uint4(
                        *(uint32_t*)&h0, *(uint32_t*)&h1,
                        *(uint32_t*)&h2, *(uint32_t*)&h3);
                    *reinterpret_cast<uint4*>(
                        &outh[(size_t)(rbase + lr) * NOUT + cc + lc]) = packed;
                } else {
                    wmma::store_matrix_sync(
                        out + (size_t)rbase * NOUT + cc,
                        acc[r][c], NOUT, wmma::mem_row_major);
                }
            }
        }
    }
}

// ===========================================================================
extern "C" void kernel_launch(void* const* d_in, const int* in_sizes, int n_in,
                              void* d_out, int out_size) {
    const float* x        = (const float*)d_in[0];
    const int*   src      = (const int*)d_in[1];
    const int*   dst      = (const int*)d_in[2];
    const float* w_self1  = (const float*)d_in[3];
    const float* w_neigh1 = (const float*)d_in[4];
    const float* b1       = (const float*)d_in[5];
    const float* w_self2  = (const float*)d_in[6];
    const float* w_neigh2 = (const float*)d_in[7];
    const float* b2       = (const float*)d_in[8];
    float* out = (float*)d_out;

    const int E = in_sizes[1];

    int *cnt, *rowptr, *cursor, *csrsrc;
    float *agg1, *agg2;
    __half *xh, *h1h;
    __nv_bfloat16 *B1h, *B1l, *B2h, *B2l;
    cudaGetSymbolAddress((void**)&cnt,    g_cnt);
    cudaGetSymbolAddress((void**)&rowptr, g_rowptr);
    cudaGetSymbolAddress((void**)&cursor, g_cursor);
    cudaGetSymbolAddress((void**)&csrsrc, g_csrsrc);
    cudaGetSymbolAddress((void**)&agg1,   g_agg1);
    cudaGetSymbolAddress((void**)&agg2,   g_agg2);
    cudaGetSymbolAddress((void**)&xh,     g_xh);
    cudaGetSymbolAddress((void**)&h1h,    g_h1h);
    cudaGetSymbolAddress((void**)&B1h,    g_B1h);
    cudaGetSymbolAddress((void**)&B1l,    g_B1l);
    cudaGetSymbolAddress((void**)&B2h,    g_B2h);
    cudaGetSymbolAddress((void**)&B2l,    g_B2l);

    constexpr int SMEM_L1 = (2 * 128 * 72 + 2 * 64 * (128 + 8)) * 2 + 16 * 128 * 4;
    constexpr int SMEM_L2 = (2 * 128 * 72 + 2 * 64 * (64 + 8)) * 2 + 16 * 64 * 4;
    cudaFuncSetAttribute((const void*)wmma_layer_kernel<D_HID, 2, 4, 2, 1, true, true>,
                         cudaFuncAttributeMaxDynamicSharedMemorySize, SMEM_L1);
    cudaFuncSetAttribute((const void*)wmma_layer_kernel<D_OUT, 1, 4, 4, 2, false, false>,
                         cudaFuncAttributeMaxDynamicSharedMemorySize, SMEM_L2);

    const int nTiles = (N_NODES + 127) / 128;
    const int E2 = E / 2;   // E is even (1e6)

    // --- CSR build ---
    zero_int_kernel<<<(N_NODES + 255) / 256, 256>>>(cnt, N_NODES);
    count_kernel<<<(E2 + 255) / 256, 256>>>((const int2*)dst, cnt, E2);
    scan_kernel<<<1, 1024>>>(cnt, rowptr, cursor, N_NODES);
    fill_kernel<<<(E2 + 255) / 256, 256>>>(
        (const int2*)src, (const int2*)dst, cursor, csrsrc, E2);

    // --- weight prep + x fp16 mirror (tiny) ---
    wprep_kernel<128, 128><<<(128 * 128 + 255) / 256, 256>>>(w_self1, w_neigh1, B1h, B1l);
    wprep_kernel<256, 64><<<(256 * 64 + 255) / 256, 256>>>(w_self2, w_neigh2, B2h, B2l);
    f2h_kernel<<<(N_NODES * D_IN / 4 + 255) / 256, 256>>>(
        (const float4*)x, (__half2*)xh, N_NODES * D_IN / 4);

    // --- Layer 1 ---
    gather_h_kernel<D_IN / 8><<<(N_NODES * (D_IN / 8) + 255) / 256, 256>>>(
        (const uint4*)xh, csrsrc, rowptr, agg1, N_NODES);
    wmma_layer_kernel<D_HID, 2, 4, 2, 1, true, true><<<nTiles, 256, SMEM_L1>>>(
        x, nullptr, agg1, B1h, B1l, b1, nullptr, h1h, N_NODES);

    // --- Layer 2 ---
    gather_h_kernel<D_HID / 8><<<(N_NODES * (D_HID / 8) + 255) / 256, 256>>>(
        (const uint4*)h1h, csrsrc, rowptr, agg2, N_NODES);
    wmma_layer_kernel<D_OUT, 1, 4, 4, 2, false, false><<<nTiles, 256, SMEM_L2>>>(
        nullptr, h1h, agg2, B2h, B2l, b2, out, nullptr, N_NODES);
}

// round 9
// speedup vs baseline: 1.6267x; 1.2599x over previous
#include <cuda_runtime.h>
#include <cuda_fp16.h>
#include <mma.h>
#include <cstdint>

using namespace nvcuda;

// ---------------------------------------------------------------------------
// GraphSAGE 2-layer forward, fp16 datapath:
//   features/aggregates stored fp16; wmma fp16 GEMM with fp32 accumulate and
//   error-compensated fp16 weight split (W = Wh + Wl): D = A@Wh + A@Wl.
//   A staging is a pure fp16 copy (no per-stage conversion instructions).
// N = 100000, E = 1e6, d_in=64, d_hid=128, d_out=64.
// ---------------------------------------------------------------------------

#define N_NODES 100000
#define E_MAX   1000000
#define D_IN    64
#define D_HID   128
#define D_OUT   64

// Scratch (device globals; no allocation allowed)
__device__ int    g_cnt   [N_NODES];
__device__ int    g_rowptr[N_NODES + 1];
__device__ int    g_cursor[N_NODES];
__device__ int    g_csrsrc[E_MAX];
__device__ __half g_xh    [N_NODES * D_IN];    // fp16 mirror of x
__device__ __half g_h1h   [N_NODES * D_HID];   // fp16 h1 (sole copy)
__device__ __half g_agg1h [N_NODES * D_IN];    // fp16 mean-agg for layer 1
__device__ __half g_agg2h [N_NODES * D_HID];   // fp16 mean-agg for layer 2
__device__ __half g_B1h[128 * 128];            // [K][N] hi(W1) fp16
__device__ __half g_B1l[128 * 128];            // lo(W1)
__device__ __half g_B2h[256 * 64];             // [K][N] hi(W2)
__device__ __half g_B2l[256 * 64];             // lo(W2)

// ===========================================================================
// CSR build
// ===========================================================================
__global__ void zero_int_kernel(int* __restrict__ p, int n) {
    int i = blockIdx.x * blockDim.x + threadIdx.x;
    if (i < n) p[i] = 0;
}

__global__ void count_kernel(const int2* __restrict__ dst2, int* __restrict__ cnt, int E2) {
    int e = blockIdx.x * blockDim.x + threadIdx.x;
    if (e < E2) {
        int2 d = dst2[e];
        atomicAdd(&cnt[d.x], 1);
        atomicAdd(&cnt[d.y], 1);
    }
}

__global__ __launch_bounds__(1024)
void scan_kernel(const int* __restrict__ cnt,
                 int* __restrict__ row_ptr,
                 int* __restrict__ cursor, int n) {
    __shared__ int sums[1024];
    const int tid = threadIdx.x;
    const int chunk = (n + 1023) / 1024;
    const int begin = tid * chunk;
    const int end = min(begin + chunk, n);
    int s = 0;
    for (int i = begin; i < end; i++) s += cnt[i];
    sums[tid] = s;
    __syncthreads();
    for (int off = 1; off < 1024; off <<= 1) {
        int v = 0;
        if (tid >= off) v = sums[tid - off];
        __syncthreads();
        if (tid >= off) sums[tid] += v;
        __syncthreads();
    }
    int prefix = (tid == 0) ? 0 : sums[tid - 1];
    for (int i = begin; i < end; i++) {
        row_ptr[i] = prefix;
        cursor[i] = prefix;
        prefix += cnt[i];
    }
    if (tid == 1023) row_ptr[n] = sums[1023];
}

__global__ void fill_kernel(const int2* __restrict__ src2,
                            const int2* __restrict__ dst2,
                            int* __restrict__ cursor,
                            int* __restrict__ csr, int E2) {
    int e = blockIdx.x * blockDim.x + threadIdx.x;
    if (e < E2) {
        int2 s = src2[e];
        int2 d = dst2[e];
        int p0 = atomicAdd(&cursor[d.x], 1);
        csr[p0] = s.x;
        int p1 = atomicAdd(&cursor[d.y], 1);
        csr[p1] = s.y;
    }
}

// fp32 -> fp16 mirror
__global__ void f2h_kernel(const float4* __restrict__ in,
                           __half2* __restrict__ out, int n4) {
    int i = blockIdx.x * blockDim.x + threadIdx.x;
    if (i >= n4) return;
    float4 v = in[i];
    out[i * 2]     = __floats2half2_rn(v.x, v.y);
    out[i * 2 + 1] = __floats2half2_rn(v.z, v.w);
}

// ===========================================================================
// Gather + mean over fp16 features, fp32 accumulation, fp16 output.
// TPN threads per node; each thread covers 8 halfs = one LDG.128 per edge.
// ===========================================================================
template <int TPN>
__global__ __launch_bounds__(256)
void gather_h_kernel(const uint4* __restrict__ feat,
                     const int* __restrict__ csr,
                     const int* __restrict__ row_ptr,
                     uint4* __restrict__ aggmean_h, int n) {
    const int tid = threadIdx.x;
    const int node = blockIdx.x * (256 / TPN) + tid / TPN;
    const int c = tid % TPN;
    if (node >= n) return;
    const int b = row_ptr[node];
    const int e = row_ptr[node + 1];
    float acc[8];
#pragma unroll
    for (int q = 0; q < 8; q++) acc[q] = 0.f;
#pragma unroll 4
    for (int i = b; i < e; i++) {
        int s = __ldg(&csr[i]);
        uint4 r = __ldg(&feat[(size_t)s * TPN + c]);
        const __half2* ph = reinterpret_cast<const __half2*>(&r);
#pragma unroll
        for (int q = 0; q < 4; q++) {
            float2 f = __half22float2(ph[q]);
            acc[2 * q]     += f.x;
            acc[2 * q + 1] += f.y;
        }
    }
    int d = e - b;
    float inv = 1.0f / (float)(d > 1 ? d : 1);
    __half2 h0 = __floats2half2_rn(acc[0] * inv, acc[1] * inv);
    __half2 h1 = __floats2half2_rn(acc[2] * inv, acc[3] * inv);
    __half2 h2 = __floats2half2_rn(acc[4] * inv, acc[5] * inv);
    __half2 h3 = __floats2half2_rn(acc[6] * inv, acc[7] * inv);
    aggmean_h[(size_t)node * TPN + c] = make_uint4(
        *(uint32_t*)&h0, *(uint32_t*)&h1, *(uint32_t*)&h2, *(uint32_t*)&h3);
}

// ===========================================================================
// Weight prep: W = [Ws; Wn] stacked -> fp16 hi/lo split, row-major [DK2][NOUT]
// ===========================================================================
template <int DK2, int NOUT>
__global__ void wprep_kernel(const float* __restrict__ ws,
                             const float* __restrict__ wn,
                             __half* __restrict__ Bh,
                             __half* __restrict__ Bl) {
    int i = blockIdx.x * blockDim.x + threadIdx.x;
    if (i >= DK2 * NOUT) return;
    int k = i / NOUT, n = i % NOUT;
    float w = (k < DK2 / 2) ? ws[k * NOUT + n] : wn[(k - DK2 / 2) * NOUT + n];
    __half hi = __float2half_rn(w);
    Bh[i] = hi;
    Bl[i] = __float2half_rn(w - __half2float(hi));
}

// ===========================================================================
// Layer via wmma fp16 GEMM with weight hi/lo compensation.
// CTA = 128 nodes x NOUT, 8 warps. Warp tile (WROWS*16) x (WCOLS*16).
// A chunks staged by straight fp16 copy (self mirror / fp16 agg).
// LAYER==1: self = xh,  agg = agg1h. Output: fp16 h1h.
// LAYER==2: self = h1h, agg = agg2h. Output: fp32 d_out.
// ===========================================================================
template <int NOUT, int WROWS, int WCOLS, int NCHUNK, int LAYER, bool RELU, bool HALF_OUT>
__global__ __launch_bounds__(256)
void wmma_layer_kernel(const __half* __restrict__ selfh,
                       const __half* __restrict__ aggh,
                       const __half* __restrict__ Bh,
                       const __half* __restrict__ Bl,
                       const float* __restrict__ bias,
                       float* __restrict__ out,
                       __half* __restrict__ outh, int nNodes) {
    constexpr int ROWU4 = (LAYER == 1) ? 8 : 16;  // fp16 source row in uint4
    constexpr int ASTR  = 72;                     // smem A row stride (halfs)
    constexpr int BSTR  = NOUT + 8;               // smem B row stride (halfs)
    constexpr int COLG  = NOUT / (WCOLS * 16);    // warp col groups

    extern __shared__ __align__(32) char smem_raw[];
    __half* sA  = (__half*)smem_raw;                 // 128 x ASTR
    __half* sBh = sA + 128 * ASTR;                   // 64 x BSTR
    __half* sBl = sBh + 64 * BSTR;                   // 64 x BSTR
    float*  sBias = (float*)(sBl + 64 * BSTR);       // 2048 floats

    const int tid = threadIdx.x;
    const int wid = tid >> 5;
    const int lane = tid & 31;
    const int rowg = wid / COLG;
    const int colg = wid % COLG;
    const int base = blockIdx.x * 128;

    for (int i = tid; i < 16 * NOUT; i += 256) sBias[i] = bias[i % NOUT];
    __syncthreads();

    wmma::fragment<wmma::accumulator, 16, 16, 16, float> acc[WROWS][WCOLS];
#pragma unroll
    for (int r = 0; r < WROWS; r++)
#pragma unroll
        for (int c = 0; c < WCOLS; c++)
            wmma::load_matrix_sync(acc[r][c],
                sBias + (colg * WCOLS + c) * 16, NOUT, wmma::mem_row_major);

    for (int kc = 0; kc < NCHUNK; kc++) {
        __syncthreads();

        // ---- stage A: straight fp16 copy, 128 rows x 64 cols ----
        const uint4* src4;
        int qoff;
        if (LAYER == 1) {
            src4 = reinterpret_cast<const uint4*>(kc ? aggh : selfh);
            qoff = 0;
        } else {
            src4 = reinterpret_cast<const uint4*>((kc < 2) ? selfh : aggh);
            qoff = (kc & 1) * 8;
        }
#pragma unroll
        for (int jj = tid; jj < 1024; jj += 256) {
            int m = jj >> 3, c8 = jj & 7;
            int node = base + m;
            uint4 v = make_uint4(0, 0, 0, 0);
            if (node < nNodes)
                v = src4[(size_t)node * ROWU4 + qoff + c8];
            *reinterpret_cast<uint4*>(&sA[m * ASTR + c8 * 8]) = v;
        }
        // ---- stage B: 64 x NOUT fp16 hi/lo ----
#pragma unroll
        for (int jj = tid; jj < 64 * NOUT / 8; jj += 256) {
            int r = jj / (NOUT / 8), c8 = jj % (NOUT / 8);
            size_t g = (size_t)(kc * 64 + r) * NOUT + c8 * 8;
            *reinterpret_cast<uint4*>(&sBh[r * BSTR + c8 * 8]) =
                *reinterpret_cast<const uint4*>(&Bh[g]);
            *reinterpret_cast<uint4*>(&sBl[r * BSTR + c8 * 8]) =
                *reinterpret_cast<const uint4*>(&Bl[g]);
        }
        __syncthreads();

        // ---- MMA over 4 k-steps of 16 ----
#pragma unroll
        for (int kk = 0; kk < 4; kk++) {
            wmma::fragment<wmma::matrix_a, 16, 16, 16, __half, wmma::row_major> a[WROWS];
#pragma unroll
            for (int r = 0; r < WROWS; r++) {
                int rr = (rowg * WROWS + r) * 16;
                wmma::load_matrix_sync(a[r], sA + rr * ASTR + kk * 16, ASTR);
            }
#pragma unroll
            for (int c = 0; c < WCOLS; c++) {
                wmma::fragment<wmma::matrix_b, 16, 16, 16, __half, wmma::row_major> bh, bl;
                int cc = (colg * WCOLS + c) * 16;
                wmma::load_matrix_sync(bh, sBh + kk * 16 * BSTR + cc, BSTR);
                wmma::load_matrix_sync(bl, sBl + kk * 16 * BSTR + cc, BSTR);
#pragma unroll
                for (int r = 0; r < WROWS; r++) {
                    wmma::mma_sync(acc[r][c], a[r], bh, acc[r][c]);
                    wmma::mma_sync(acc[r][c], a[r], bl, acc[r][c]);
                }
            }
        }
    }

    // ---- epilogue ----
    float* scratch = sBias + wid * 256;   // per-warp 16x16 fp32 tile
#pragma unroll
    for (int r = 0; r < WROWS; r++) {
        int rbase = base + (rowg * WROWS + r) * 16;
        if (rbase < nNodes) {
#pragma unroll
            for (int c = 0; c < WCOLS; c++) {
                if (RELU) {
#pragma unroll
                    for (int i = 0; i < acc[r][c].num_elements; i++)
                        acc[r][c].x[i] = fmaxf(acc[r][c].x[i], 0.f);
                }
                int cc = (colg * WCOLS + c) * 16;
                if (HALF_OUT) {
                    __syncwarp();
                    wmma::store_matrix_sync(scratch, acc[r][c], 16,
                                            wmma::mem_row_major);
                    __syncwarp();
                    int lr = lane >> 1, lc = (lane & 1) * 8;
                    float4 va = *reinterpret_cast<float4*>(&scratch[lr * 16 + lc]);
                    float4 vb = *reinterpret_cast<float4*>(&scratch[lr * 16 + lc + 4]);
                    __half2 h0 = __floats2half2_rn(va.x, va.y);
                    __half2 h1 = __floats2half2_rn(va.z, va.w);
                    __half2 h2 = __floats2half2_rn(vb.x, vb.y);
                    __half2 h3 = __floats2half2_rn(vb.z, vb.w);
                    uint4 packed = make_uint4(
                        *(uint32_t*)&h0, *(uint32_t*)&h1,
                        *(uint32_t*)&h2, *(uint32_t*)&h3);
                    *reinterpret_cast<uint4*>(
                        &outh[(size_t)(rbase + lr) * NOUT + cc + lc]) = packed;
                } else {
                    wmma::store_matrix_sync(
                        out + (size_t)rbase * NOUT + cc,
                        acc[r][c], NOUT, wmma::mem_row_major);
                }
            }
        }
    }
}

// ===========================================================================
extern "C" void kernel_launch(void* const* d_in, const int* in_sizes, int n_in,
                              void* d_out, int out_size) {
    const float* x        = (const float*)d_in[0];
    const int*   src      = (const int*)d_in[1];
    const int*   dst      = (const int*)d_in[2];
    const float* w_self1  = (const float*)d_in[3];
    const float* w_neigh1 = (const float*)d_in[4];
    const float* b1       = (const float*)d_in[5];
    const float* w_self2  = (const float*)d_in[6];
    const float* w_neigh2 = (const float*)d_in[7];
    const float* b2       = (const float*)d_in[8];
    float* out = (float*)d_out;

    const int E = in_sizes[1];

    int *cnt, *rowptr, *cursor, *csrsrc;
    __half *xh, *h1h, *agg1h, *agg2h;
    __half *B1h, *B1l, *B2h, *B2l;
    cudaGetSymbolAddress((void**)&cnt,    g_cnt);
    cudaGetSymbolAddress((void**)&rowptr, g_rowptr);
    cudaGetSymbolAddress((void**)&cursor, g_cursor);
    cudaGetSymbolAddress((void**)&csrsrc, g_csrsrc);
    cudaGetSymbolAddress((void**)&xh,     g_xh);
    cudaGetSymbolAddress((void**)&h1h,    g_h1h);
    cudaGetSymbolAddress((void**)&agg1h,  g_agg1h);
    cudaGetSymbolAddress((void**)&agg2h,  g_agg2h);
    cudaGetSymbolAddress((void**)&B1h,    g_B1h);
    cudaGetSymbolAddress((void**)&B1l,    g_B1l);
    cudaGetSymbolAddress((void**)&B2h,    g_B2h);
    cudaGetSymbolAddress((void**)&B2l,    g_B2l);

    // smem: A (128x72 half) + B hi/lo (2 x 64 x (NOUT+8) half) + 2048 floats
    constexpr int SMEM_L1 = 128 * 72 * 2 + 2 * 64 * (128 + 8) * 2 + 2048 * 4; // 61440
    constexpr int SMEM_L2 = 128 * 72 * 2 + 2 * 64 * (64 + 8) * 2 + 2048 * 4;  // 45056
    cudaFuncSetAttribute((const void*)wmma_layer_kernel<D_HID, 2, 4, 2, 1, true, true>,
                         cudaFuncAttributeMaxDynamicSharedMemorySize, SMEM_L1);
    cudaFuncSetAttribute((const void*)wmma_layer_kernel<D_OUT, 1, 4, 4, 2, false, false>,
                         cudaFuncAttributeMaxDynamicSharedMemorySize, SMEM_L2);

    const int nTiles = (N_NODES + 127) / 128;
    const int E2 = E / 2;   // E is even (1e6)

    // --- CSR build ---
    zero_int_kernel<<<(N_NODES + 255) / 256, 256>>>(cnt, N_NODES);
    count_kernel<<<(E2 + 255) / 256, 256>>>((const int2*)dst, cnt, E2);
    scan_kernel<<<1, 1024>>>(cnt, rowptr, cursor, N_NODES);
    fill_kernel<<<(E2 + 255) / 256, 256>>>(
        (const int2*)src, (const int2*)dst, cursor, csrsrc, E2);

    // --- weight prep + x fp16 mirror (tiny) ---
    wprep_kernel<128, 128><<<(128 * 128 + 255) / 256, 256>>>(w_self1, w_neigh1, B1h, B1l);
    wprep_kernel<256, 64><<<(256 * 64 + 255) / 256, 256>>>(w_self2, w_neigh2, B2h, B2l);
    f2h_kernel<<<(N_NODES * D_IN / 4 + 255) / 256, 256>>>(
        (const float4*)x, (__half2*)xh, N_NODES * D_IN / 4);

    // --- Layer 1 ---
    gather_h_kernel<D_IN / 8><<<(N_NODES * (D_IN / 8) + 255) / 256, 256>>>(
        (const uint4*)xh, csrsrc, rowptr, (uint4*)agg1h, N_NODES);
    wmma_layer_kernel<D_HID, 2, 4, 2, 1, true, true><<<nTiles, 256, SMEM_L1>>>(
        xh, agg1h, B1h, B1l, b1, nullptr, h1h, N_NODES);

    // --- Layer 2 ---
    gather_h_kernel<D_HID / 8><<<(N_NODES * (D_HID / 8) + 255) / 256, 256>>>(
        (const uint4*)h1h, csrsrc, rowptr, (uint4*)agg2h, N_NODES);
    wmma_layer_kernel<D_OUT, 1, 4, 4, 2, false, false><<<nTiles, 256, SMEM_L2>>>(
        h1h, agg2h, B2h, B2l, b2, out, nullptr, N_NODES);
}

// round 10
// speedup vs baseline: 1.6597x; 1.0203x over previous
#include <cuda_runtime.h>
#include <cuda_fp16.h>
#include <mma.h>
#include <cstdint>

using namespace nvcuda;

// ---------------------------------------------------------------------------
// GraphSAGE 2-layer forward, fp16 datapath:
//   features/aggregates stored fp16; gathers accumulate edge-pairs via HADD2
//   then fp32; wmma fp16 GEMM with fp32 accumulate and error-compensated
//   fp16 weight split (W = Wh + Wl): D = A@Wh + A@Wl.
// N = 100000, E = 1e6, d_in=64, d_hid=128, d_out=64.
// ---------------------------------------------------------------------------

#define N_NODES 100000
#define E_MAX   1000000
#define D_IN    64
#define D_HID   128
#define D_OUT   64

// Scratch (device globals; no allocation allowed)
__device__ int    g_cnt   [N_NODES];
__device__ int    g_rowptr[N_NODES + 1];
__device__ int    g_cursor[N_NODES];
__device__ int    g_csrsrc[E_MAX];
__device__ __half g_xh    [N_NODES * D_IN];    // fp16 mirror of x
__device__ __half g_h1h   [N_NODES * D_HID];   // fp16 h1 (sole copy)
__device__ __half g_agg1h [N_NODES * D_IN];    // fp16 mean-agg for layer 1
__device__ __half g_agg2h [N_NODES * D_HID];   // fp16 mean-agg for layer 2
__device__ __half g_B1h[128 * 128];            // [K][N] hi(W1) fp16
__device__ __half g_B1l[128 * 128];            // lo(W1)
__device__ __half g_B2h[256 * 64];             // [K][N] hi(W2)
__device__ __half g_B2l[256 * 64];             // lo(W2)

// ===========================================================================
// CSR build
// ===========================================================================
__global__ void zero_int_kernel(int4* __restrict__ p, int n4) {
    int i = blockIdx.x * blockDim.x + threadIdx.x;
    if (i < n4) p[i] = make_int4(0, 0, 0, 0);
}

__global__ void count_kernel(const int2* __restrict__ dst2, int* __restrict__ cnt, int E2) {
    int e = blockIdx.x * blockDim.x + threadIdx.x;
    if (e < E2) {
        int2 d = dst2[e];
        atomicAdd(&cnt[d.x], 1);
        atomicAdd(&cnt[d.y], 1);
    }
}

__global__ __launch_bounds__(1024)
void scan_kernel(const int* __restrict__ cnt,
                 int* __restrict__ row_ptr,
                 int* __restrict__ cursor, int n) {
    __shared__ int sums[1024];
    const int tid = threadIdx.x;
    const int chunk = (n + 1023) / 1024;
    const int begin = tid * chunk;
    const int end = min(begin + chunk, n);
    int s = 0;
    for (int i = begin; i < end; i++) s += cnt[i];
    sums[tid] = s;
    __syncthreads();
    for (int off = 1; off < 1024; off <<= 1) {
        int v = 0;
        if (tid >= off) v = sums[tid - off];
        __syncthreads();
        if (tid >= off) sums[tid] += v;
        __syncthreads();
    }
    int prefix = (tid == 0) ? 0 : sums[tid - 1];
    for (int i = begin; i < end; i++) {
        row_ptr[i] = prefix;
        cursor[i] = prefix;
        prefix += cnt[i];
    }
    if (tid == 1023) row_ptr[n] = sums[1023];
}

__global__ void fill_kernel(const int2* __restrict__ src2,
                            const int2* __restrict__ dst2,
                            int* __restrict__ cursor,
                            int* __restrict__ csr, int E2) {
    int e = blockIdx.x * blockDim.x + threadIdx.x;
    if (e < E2) {
        int2 s = src2[e];
        int2 d = dst2[e];
        int p0 = atomicAdd(&cursor[d.x], 1);
        csr[p0] = s.x;
        int p1 = atomicAdd(&cursor[d.y], 1);
        csr[p1] = s.y;
    }
}

// fp32 -> fp16 mirror
__global__ void f2h_kernel(const float4* __restrict__ in,
                           __half2* __restrict__ out, int n4) {
    int i = blockIdx.x * blockDim.x + threadIdx.x;
    if (i >= n4) return;
    float4 v = in[i];
    out[i * 2]     = __floats2half2_rn(v.x, v.y);
    out[i * 2 + 1] = __floats2half2_rn(v.z, v.w);
}

// ===========================================================================
// Gather + mean over fp16 features. Edge-pairs summed in fp16 (HADD2) then
// accumulated in fp32 (no fp16 drift: running sum stays fp32).
// TPN threads per node; each thread covers 8 halfs = one LDG.128 per edge.
// ===========================================================================
template <int TPN>
__global__ __launch_bounds__(256)
void gather_h_kernel(const uint4* __restrict__ feat,
                     const int* __restrict__ csr,
                     const int* __restrict__ row_ptr,
                     uint4* __restrict__ aggmean_h, int n) {
    const int tid = threadIdx.x;
    const int node = blockIdx.x * (256 / TPN) + tid / TPN;
    const int c = tid % TPN;
    if (node >= n) return;
    const int b = row_ptr[node];
    const int e = row_ptr[node + 1];
    float acc[8];
#pragma unroll
    for (int q = 0; q < 8; q++) acc[q] = 0.f;

    int i = b;
#pragma unroll 2
    for (; i + 1 < e; i += 2) {
        int s0 = __ldg(&csr[i]);
        int s1 = __ldg(&csr[i + 1]);
        uint4 r0 = __ldg(&feat[(size_t)s0 * TPN + c]);
        uint4 r1 = __ldg(&feat[(size_t)s1 * TPN + c]);
        const __half2* p0 = reinterpret_cast<const __half2*>(&r0);
        const __half2* p1 = reinterpret_cast<const __half2*>(&r1);
#pragma unroll
        for (int q = 0; q < 4; q++) {
            __half2 hs = __hadd2(p0[q], p1[q]);   // one fp16 rounding per term
            float2 f = __half22float2(hs);
            acc[2 * q]     += f.x;
            acc[2 * q + 1] += f.y;
        }
    }
    if (i < e) {   // odd tail
        int s = __ldg(&csr[i]);
        uint4 r = __ldg(&feat[(size_t)s * TPN + c]);
        const __half2* ph = reinterpret_cast<const __half2*>(&r);
#pragma unroll
        for (int q = 0; q < 4; q++) {
            float2 f = __half22float2(ph[q]);
            acc[2 * q]     += f.x;
            acc[2 * q + 1] += f.y;
        }
    }

    int d = e - b;
    float inv = 1.0f / (float)(d > 1 ? d : 1);
    __half2 h0 = __floats2half2_rn(acc[0] * inv, acc[1] * inv);
    __half2 h1 = __floats2half2_rn(acc[2] * inv, acc[3] * inv);
    __half2 h2 = __floats2half2_rn(acc[4] * inv, acc[5] * inv);
    __half2 h3 = __floats2half2_rn(acc[6] * inv, acc[7] * inv);
    aggmean_h[(size_t)node * TPN + c] = make_uint4(
        *(uint32_t*)&h0, *(uint32_t*)&h1, *(uint32_t*)&h2, *(uint32_t*)&h3);
}

// ===========================================================================
// Weight prep: W = [Ws; Wn] stacked -> fp16 hi/lo split, row-major [DK2][NOUT]
// ===========================================================================
template <int DK2, int NOUT>
__global__ void wprep_kernel(const float* __restrict__ ws,
                             const float* __restrict__ wn,
                             __half* __restrict__ Bh,
                             __half* __restrict__ Bl) {
    int i = blockIdx.x * blockDim.x + threadIdx.x;
    if (i >= DK2 * NOUT) return;
    int k = i / NOUT, n = i % NOUT;
    float w = (k < DK2 / 2) ? ws[k * NOUT + n] : wn[(k - DK2 / 2) * NOUT + n];
    __half hi = __float2half_rn(w);
    Bh[i] = hi;
    Bl[i] = __float2half_rn(w - __half2float(hi));
}

// ===========================================================================
// Layer via wmma fp16 GEMM with weight hi/lo compensation.
// CTA = 128 nodes x NOUT, 8 warps. Warp tile (WROWS*16) x (WCOLS*16).
// A chunks staged by straight fp16 copy (self mirror / fp16 agg).
// LAYER==1: self = xh,  agg = agg1h. Output: fp16 h1h.
// LAYER==2: self = h1h, agg = agg2h. Output: fp32 d_out.
// ===========================================================================
template <int NOUT, int WROWS, int WCOLS, int NCHUNK, int LAYER, bool RELU, bool HALF_OUT>
__global__ __launch_bounds__(256)
void wmma_layer_kernel(const __half* __restrict__ selfh,
                       const __half* __restrict__ aggh,
                       const __half* __restrict__ Bh,
                       const __half* __restrict__ Bl,
                       const float* __restrict__ bias,
                       float* __restrict__ out,
                       __half* __restrict__ outh, int nNodes) {
    constexpr int ROWU4 = (LAYER == 1) ? 8 : 16;  // fp16 source row in uint4
    constexpr int ASTR  = 72;                     // smem A row stride (halfs)
    constexpr int BSTR  = NOUT + 8;               // smem B row stride (halfs)
    constexpr int COLG  = NOUT / (WCOLS * 16);    // warp col groups

    extern __shared__ __align__(32) char smem_raw[];
    __half* sA  = (__half*)smem_raw;                 // 128 x ASTR
    __half* sBh = sA + 128 * ASTR;                   // 64 x BSTR
    __half* sBl = sBh + 64 * BSTR;                   // 64 x BSTR
    float*  sBias = (float*)(sBl + 64 * BSTR);       // 2048 floats

    const int tid = threadIdx.x;
    const int wid = tid >> 5;
    const int lane = tid & 31;
    const int rowg = wid / COLG;
    const int colg = wid % COLG;
    const int base = blockIdx.x * 128;

    for (int i = tid; i < 16 * NOUT; i += 256) sBias[i] = bias[i % NOUT];
    __syncthreads();

    wmma::fragment<wmma::accumulator, 16, 16, 16, float> acc[WROWS][WCOLS];
#pragma unroll
    for (int r = 0; r < WROWS; r++)
#pragma unroll
        for (int c = 0; c < WCOLS; c++)
            wmma::load_matrix_sync(acc[r][c],
                sBias + (colg * WCOLS + c) * 16, NOUT, wmma::mem_row_major);

    for (int kc = 0; kc < NCHUNK; kc++) {
        __syncthreads();

        // ---- stage A: straight fp16 copy, 128 rows x 64 cols ----
        const uint4* src4;
        int qoff;
        if (LAYER == 1) {
            src4 = reinterpret_cast<const uint4*>(kc ? aggh : selfh);
            qoff = 0;
        } else {
            src4 = reinterpret_cast<const uint4*>((kc < 2) ? selfh : aggh);
            qoff = (kc & 1) * 8;
        }
#pragma unroll
        for (int jj = tid; jj < 1024; jj += 256) {
            int m = jj >> 3, c8 = jj & 7;
            int node = base + m;
            uint4 v = make_uint4(0, 0, 0, 0);
            if (node < nNodes)
                v = src4[(size_t)node * ROWU4 + qoff + c8];
            *reinterpret_cast<uint4*>(&sA[m * ASTR + c8 * 8]) = v;
        }
        // ---- stage B: 64 x NOUT fp16 hi/lo ----
#pragma unroll
        for (int jj = tid; jj < 64 * NOUT / 8; jj += 256) {
            int r = jj / (NOUT / 8), c8 = jj % (NOUT / 8);
            size_t g = (size_t)(kc * 64 + r) * NOUT + c8 * 8;
            *reinterpret_cast<uint4*>(&sBh[r * BSTR + c8 * 8]) =
                *reinterpret_cast<const uint4*>(&Bh[g]);
            *reinterpret_cast<uint4*>(&sBl[r * BSTR + c8 * 8]) =
                *reinterpret_cast<const uint4*>(&Bl[g]);
        }
        __syncthreads();

        // ---- MMA over 4 k-steps of 16 ----
#pragma unroll
        for (int kk = 0; kk < 4; kk++) {
            wmma::fragment<wmma::matrix_a, 16, 16, 16, __half, wmma::row_major> a[WROWS];
#pragma unroll
            for (int r = 0; r < WROWS; r++) {
                int rr = (rowg * WROWS + r) * 16;
                wmma::load_matrix_sync(a[r], sA + rr * ASTR + kk * 16, ASTR);
            }
#pragma unroll
            for (int c = 0; c < WCOLS; c++) {
                wmma::fragment<wmma::matrix_b, 16, 16, 16, __half, wmma::row_major> bh, bl;
                int cc = (colg * WCOLS + c) * 16;
                wmma::load_matrix_sync(bh, sBh + kk * 16 * BSTR + cc, BSTR);
                wmma::load_matrix_sync(bl, sBl + kk * 16 * BSTR + cc, BSTR);
#pragma unroll
                for (int r = 0; r < WROWS; r++) {
                    wmma::mma_sync(acc[r][c], a[r], bh, acc[r][c]);
                    wmma::mma_sync(acc[r][c], a[r], bl, acc[r][c]);
                }
            }
        }
    }

    // ---- epilogue ----
    float* scratch = sBias + wid * 256;   // per-warp 16x16 fp32 tile
#pragma unroll
    for (int r = 0; r < WROWS; r++) {
        int rbase = base + (rowg * WROWS + r) * 16;
        if (rbase < nNodes) {
#pragma unroll
            for (int c = 0; c < WCOLS; c++) {
                if (RELU) {
#pragma unroll
                    for (int i = 0; i < acc[r][c].num_elements; i++)
                        acc[r][c].x[i] = fmaxf(acc[r][c].x[i], 0.f);
                }
                int cc = (colg * WCOLS + c) * 16;
                if (HALF_OUT) {
                    __syncwarp();
                    wmma::store_matrix_sync(scratch, acc[r][c], 16,
                                            wmma::mem_row_major);
                    __syncwarp();
                    int lr = lane >> 1, lc = (lane & 1) * 8;
                    float4 va = *reinterpret_cast<float4*>(&scratch[lr * 16 + lc]);
                    float4 vb = *reinterpret_cast<float4*>(&scratch[lr * 16 + lc + 4]);
                    __half2 h0 = __floats2half2_rn(va.x, va.y);
                    __half2 h1 = __floats2half2_rn(va.z, va.w);
                    __half2 h2 = __floats2half2_rn(vb.x, vb.y);
                    __half2 h3 = __floats2half2_rn(vb.z, vb.w);
                    uint4 packed = make_uint4(
                        *(uint32_t*)&h0, *(uint32_t*)&h1,
                        *(uint32_t*)&h2, *(uint32_t*)&h3);
                    *reinterpret_cast<uint4*>(
                        &outh[(size_t)(rbase + lr) * NOUT + cc + lc]) = packed;
                } else {
                    wmma::store_matrix_sync(
                        out + (size_t)rbase * NOUT + cc,
                        acc[r][c], NOUT, wmma::mem_row_major);
                }
            }
        }
    }
}

// ===========================================================================
extern "C" void kernel_launch(void* const* d_in, const int* in_sizes, int n_in,
                              void* d_out, int out_size) {
    const float* x        = (const float*)d_in[0];
    const int*   src      = (const int*)d_in[1];
    const int*   dst      = (const int*)d_in[2];
    const float* w_self1  = (const float*)d_in[3];
    const float* w_neigh1 = (const float*)d_in[4];
    const float* b1       = (const float*)d_in[5];
    const float* w_self2  = (const float*)d_in[6];
    const float* w_neigh2 = (const float*)d_in[7];
    const float* b2       = (const float*)d_in[8];
    float* out = (float*)d_out;

    const int E = in_sizes[1];

    int *cnt, *rowptr, *cursor, *csrsrc;
    __half *xh, *h1h, *agg1h, *agg2h;
    __half *B1h, *B1l, *B2h, *B2l;
    cudaGetSymbolAddress((void**)&cnt,    g_cnt);
    cudaGetSymbolAddress((void**)&rowptr, g_rowptr);
    cudaGetSymbolAddress((void**)&cursor, g_cursor);
    cudaGetSymbolAddress((void**)&csrsrc, g_csrsrc);
    cudaGetSymbolAddress((void**)&xh,     g_xh);
    cudaGetSymbolAddress((void**)&h1h,    g_h1h);
    cudaGetSymbolAddress((void**)&agg1h,  g_agg1h);
    cudaGetSymbolAddress((void**)&agg2h,  g_agg2h);
    cudaGetSymbolAddress((void**)&B1h,    g_B1h);
    cudaGetSymbolAddress((void**)&B1l,    g_B1l);
    cudaGetSymbolAddress((void**)&B2h,    g_B2h);
    cudaGetSymbolAddress((void**)&B2l,    g_B2l);

    // smem: A (128x72 half) + B hi/lo (2 x 64 x (NOUT+8) half) + 2048 floats
    constexpr int SMEM_L1 = 128 * 72 * 2 + 2 * 64 * (128 + 8) * 2 + 2048 * 4; // 61440
    constexpr int SMEM_L2 = 128 * 72 * 2 + 2 * 64 * (64 + 8) * 2 + 2048 * 4;  // 45056
    cudaFuncSetAttribute((const void*)wmma_layer_kernel<D_HID, 2, 4, 2, 1, true, true>,
                         cudaFuncAttributeMaxDynamicSharedMemorySize, SMEM_L1);
    cudaFuncSetAttribute((const void*)wmma_layer_kernel<D_OUT, 1, 4, 4, 2, false, false>,
                         cudaFuncAttributeMaxDynamicSharedMemorySize, SMEM_L2);

    const int nTiles = (N_NODES + 127) / 128;
    const int E2 = E / 2;   // E is even (1e6)

    // --- CSR build ---
    zero_int_kernel<<<(N_NODES / 4 + 255) / 256, 256>>>((int4*)cnt, N_NODES / 4);
    count_kernel<<<(E2 + 255) / 256, 256>>>((const int2*)dst, cnt, E2);
    scan_kernel<<<1, 1024>>>(cnt, rowptr, cursor, N_NODES);
    fill_kernel<<<(E2 + 255) / 256, 256>>>(
        (const int2*)src, (const int2*)dst, cursor, csrsrc, E2);

    // --- weight prep + x fp16 mirror (tiny) ---
    wprep_kernel<128, 128><<<(128 * 128 + 255) / 256, 256>>>(w_self1, w_neigh1, B1h, B1l);
    wprep_kernel<256, 64><<<(256 * 64 + 255) / 256, 256>>>(w_self2, w_neigh2, B2h, B2l);
    f2h_kernel<<<(N_NODES * D_IN / 4 + 255) / 256, 256>>>(
        (const float4*)x, (__half2*)xh, N_NODES * D_IN / 4);

    // --- Layer 1 ---
    gather_h_kernel<D_IN / 8><<<(N_NODES * (D_IN / 8) + 255) / 256, 256>>>(
        (const uint4*)xh, csrsrc, rowptr, (uint4*)agg1h, N_NODES);
    wmma_layer_kernel<D_HID, 2, 4, 2, 1, true, true><<<nTiles, 256, SMEM_L1>>>(
        xh, agg1h, B1h, B1l, b1, nullptr, h1h, N_NODES);

    // --- Layer 2 ---
    gather_h_kernel<D_HID / 8><<<(N_NODES * (D_HID / 8) + 255) / 256, 256>>>(
        (const uint4*)h1h, csrsrc, rowptr, (uint4*)agg2h, N_NODES);
    wmma_layer_kernel<D_OUT, 1, 4, 4, 2, false, false><<<nTiles, 256, SMEM_L2>>>(
        h1h, agg2h, B2h, B2l, b2, out, nullptr, N_NODES);
}